// round 14
// baseline (speedup 1.0000x reference)
#include <cuda_runtime.h>
#include <cuda_bf16.h>

// ---------------------------------------------------------------------------
// EdgeClassifierGNN: 2x SAGEConv(mean) + edge MLP.
// Linearity refactor: mean_agg(X) @ W == mean_agg(X @ W), so each layer is
//   PQ = X @ [Wl | Wr]                (one N=512 tf32 GEMM, cp.async 2-stage)
//   h  = relu( rdeg * sum_src P[src] + Q[node] + b )   (fused CSR gather)
// Edge MLP factored: AB = h2 @ [Wm1_top | Wm1_bot] (same GEMM shape)
//   out[e] = relu(AB[src,:256]+AB[dst,256:]+bm1) @ Wm2 + bm2
// ---------------------------------------------------------------------------

#define MAXN 50000
#define MAXE 800000
#define D 256
#define LDAB 512

__device__ __align__(16) float g_PQ [(size_t)MAXN * LDAB];
__device__ __align__(16) float g_rdeg[MAXN];
__device__ __align__(16) float g_h1  [(size_t)MAXN * D];
__device__ __align__(16) float g_h2  [(size_t)MAXN * D];
__device__ __align__(16) float g_AB  [(size_t)MAXN * LDAB];
__device__ int g_deg   [MAXN];
__device__ int g_rowptr[MAXN + 1];
__device__ int g_cursor[MAXN];
__device__ int g_elist [MAXE];

// ---------------------------------------------------------------- zero int
__global__ void zeroi_kernel(int* __restrict__ p, int n) {
    int i = blockIdx.x * blockDim.x + threadIdx.x;
    if (i < n) p[i] = 0;
}

// ---------------------------------------------------------------- histogram
__global__ void hist_kernel(const int* __restrict__ ei, int* __restrict__ deg,
                            int E)
{
    int e = blockIdx.x * blockDim.x + threadIdx.x;
    if (e < E) atomicAdd(deg + ei[E + e], 1);
}

// ---------------------------------------------------------------- scan
__global__ void scan_kernel(const int* __restrict__ deg,
                            int* __restrict__ rowptr, int* __restrict__ cursor,
                            float* __restrict__ rdeg, int n)
{
    __shared__ int sdata[1024];
    __shared__ int carry_s;
    if (threadIdx.x == 0) carry_s = 0;
    __syncthreads();

    for (int base = 0; base < n; base += 1024) {
        int i = base + threadIdx.x;
        int v = (i < n) ? deg[i] : 0;
        sdata[threadIdx.x] = v;
        __syncthreads();
#pragma unroll
        for (int off = 1; off < 1024; off <<= 1) {
            int t = (threadIdx.x >= off) ? sdata[threadIdx.x - off] : 0;
            __syncthreads();
            sdata[threadIdx.x] += t;
            __syncthreads();
        }
        int incl = sdata[threadIdx.x] + carry_s;
        if (i < n) {
            rowptr[i + 1] = incl;
            cursor[i]     = incl - v;
            rdeg[i]       = 1.0f / fmaxf((float)v, 1.0f);
        }
        __syncthreads();
        if (threadIdx.x == 1023) carry_s = incl;
        __syncthreads();
    }
    if (threadIdx.x == 0) rowptr[0] = 0;
}

// ---------------------------------------------------------------- fill
__global__ void fill_kernel(const int* __restrict__ ei, int* __restrict__ cursor,
                            int* __restrict__ elist, int E)
{
    int e = blockIdx.x * blockDim.x + threadIdx.x;
    if (e >= E) return;
    int p = atomicAdd(cursor + ei[E + e], 1);
    elist[p] = ei[e];              // store src
}

// ---------------------------------------------------------------- fused gather
// warp per node:
//   h[node] = relu( rdeg[node] * sum_{s in row} PQ[s, 0:256]
//                   + PQ[node, 256:512] + bias )
__global__ void __launch_bounds__(256) gatherf_kernel(
    const int* __restrict__ rowptr, const int* __restrict__ elist,
    const float* __restrict__ rdeg, const float* __restrict__ PQ,
    const float* __restrict__ bias, float* __restrict__ outH, int M)
{
    int node = blockIdx.x * 8 + (threadIdx.x >> 5);
    if (node >= M) return;
    int lane = threadIdx.x & 31;
    int q0 = lane, q1 = lane + 32;
    int beg = rowptr[node], end = rowptr[node + 1];

    float4 a0 = make_float4(0.f, 0.f, 0.f, 0.f);
    float4 a1 = make_float4(0.f, 0.f, 0.f, 0.f);

    int i = beg;
    for (; i + 3 < end; i += 4) {
        int s0 = elist[i],     s1 = elist[i + 1];
        int s2 = elist[i + 2], s3 = elist[i + 3];
        const float4* x0 = (const float4*)(PQ + (size_t)s0 * LDAB);
        const float4* x1 = (const float4*)(PQ + (size_t)s1 * LDAB);
        const float4* x2 = (const float4*)(PQ + (size_t)s2 * LDAB);
        const float4* x3 = (const float4*)(PQ + (size_t)s3 * LDAB);
        float4 u0 = x0[q0], v0 = x1[q0], w0 = x2[q0], z0 = x3[q0];
        float4 u1 = x0[q1], v1 = x1[q1], w1 = x2[q1], z1 = x3[q1];
        a0.x += (u0.x + v0.x) + (w0.x + z0.x);
        a0.y += (u0.y + v0.y) + (w0.y + z0.y);
        a0.z += (u0.z + v0.z) + (w0.z + z0.z);
        a0.w += (u0.w + v0.w) + (w0.w + z0.w);
        a1.x += (u1.x + v1.x) + (w1.x + z1.x);
        a1.y += (u1.y + v1.y) + (w1.y + z1.y);
        a1.z += (u1.z + v1.z) + (w1.z + z1.z);
        a1.w += (u1.w + v1.w) + (w1.w + z1.w);
    }
    for (; i < end; i++) {
        int s0 = elist[i];
        const float4* x0 = (const float4*)(PQ + (size_t)s0 * LDAB);
        float4 u0 = x0[q0], u1 = x0[q1];
        a0.x += u0.x; a0.y += u0.y; a0.z += u0.z; a0.w += u0.w;
        a1.x += u1.x; a1.y += u1.y; a1.z += u1.z; a1.w += u1.w;
    }

    float r = rdeg[node];
    const float4* qrow = (const float4*)(PQ + (size_t)node * LDAB + D);
    const float4* brow = (const float4*)bias;
    float4 qv0 = qrow[q0], qv1 = qrow[q1];
    float4 bv0 = brow[q0], bv1 = brow[q1];

    float4 o0, o1;
    o0.x = fmaxf(fmaf(a0.x, r, qv0.x + bv0.x), 0.f);
    o0.y = fmaxf(fmaf(a0.y, r, qv0.y + bv0.y), 0.f);
    o0.z = fmaxf(fmaf(a0.z, r, qv0.z + bv0.z), 0.f);
    o0.w = fmaxf(fmaf(a0.w, r, qv0.w + bv0.w), 0.f);
    o1.x = fmaxf(fmaf(a1.x, r, qv1.x + bv1.x), 0.f);
    o1.y = fmaxf(fmaf(a1.y, r, qv1.y + bv1.y), 0.f);
    o1.z = fmaxf(fmaf(a1.z, r, qv1.z + bv1.z), 0.f);
    o1.w = fmaxf(fmaf(a1.w, r, qv1.w + bv1.w), 0.f);

    float4* o = (float4*)(outH + (size_t)node * D);
    o[q0] = o0;
    o[q1] = o1;
}

// ---------------------------------------------------------------- tf32 GEMM
// C[M, 512] = A[M,256] @ [Blo | Bhi]   (blocks n0<256 -> Blo, else Bhi)
// cp.async double-buffered, mma.sync m16n8k8 tf32, fp32 accum. ldc = 512.
#define GBM 128
#define GBN 128
#define GBK 16
#define AS_STRIDE 20
#define BS_STRIDE 136
#define KSTEPS (D / GBK)   // 16

__device__ __forceinline__ unsigned f2tf32(float f) {
    unsigned u;
    asm("cvt.rna.tf32.f32 %0, %1;" : "=r"(u) : "f"(f));
    return u;
}

__device__ __forceinline__ void cpa16(unsigned dst, const void* src, int nbytes) {
    asm volatile("cp.async.cg.shared.global [%0], [%1], 16, %2;\n"
                 :: "r"(dst), "l"(src), "r"(nbytes));
}

__global__ void __launch_bounds__(256) mma_gemm_kernel(
    const float* __restrict__ A1, const float* __restrict__ Blo,
    const float* __restrict__ Bhi,
    float* __restrict__ C, int M)
{
    __shared__ float As[2][GBM * AS_STRIDE];
    __shared__ float Bs[2][GBK * BS_STRIDE];

    int tid    = threadIdx.x;
    int warp   = tid >> 5;
    int lane   = tid & 31;
    int warp_m = warp >> 2;
    int warp_n = warp & 3;
    int m0 = blockIdx.y * GBM;
    int n0 = blockIdx.x * GBN;

    const float* Bg = (n0 >= 256) ? Bhi : Blo;
    int nb = (n0 >= 256) ? (n0 - 256) : n0;

    int ar  = lane >> 2;
    int ac  = lane & 3;
    int ac2 = ac * 2;

    float c[4][4][4];
#pragma unroll
    for (int i = 0; i < 4; i++)
#pragma unroll
        for (int j = 0; j < 4; j++)
#pragma unroll
            for (int r = 0; r < 4; r++) c[i][j][r] = 0.f;

    unsigned asb[2], bsb[2];
    asb[0] = (unsigned)__cvta_generic_to_shared(&As[0][0]);
    asb[1] = (unsigned)__cvta_generic_to_shared(&As[1][0]);
    bsb[0] = (unsigned)__cvta_generic_to_shared(&Bs[0][0]);
    bsb[1] = (unsigned)__cvta_generic_to_shared(&Bs[1][0]);

    auto issue = [&](int t, int buf) {
        int k0 = t * GBK;
#pragma unroll
        for (int u = 0; u < 2; u++) {
            int idx = u * 256 + tid;
            int row = idx >> 2;
            int kq  = (idx & 3) * 4;
            int gm  = m0 + row;
            bool ok = (gm < M);
            const float* src = A1 + (size_t)(ok ? gm : 0) * D + k0 + kq;
            cpa16(asb[buf] + (unsigned)(row * AS_STRIDE + kq) * 4, src, ok ? 16 : 0);
        }
#pragma unroll
        for (int u = 0; u < 2; u++) {
            int idx = u * 256 + tid;
            int row = idx >> 5;
            int nq  = (idx & 31) * 4;
            cpa16(bsb[buf] + (unsigned)(row * BS_STRIDE + nq) * 4,
                  Bg + (size_t)(k0 + row) * D + nb + nq, 16);
        }
        asm volatile("cp.async.commit_group;\n" ::: "memory");
    };

    issue(0, 0);

    for (int t = 0; t < KSTEPS; t++) {
        int buf = t & 1;
        if (t + 1 < KSTEPS) {
            issue(t + 1, buf ^ 1);
            asm volatile("cp.async.wait_group 1;\n" ::: "memory");
        } else {
            asm volatile("cp.async.wait_group 0;\n" ::: "memory");
        }
        __syncthreads();

        const float* Asb = As[buf];
        const float* Bsb = Bs[buf];
#pragma unroll
        for (int k8 = 0; k8 < GBK; k8 += 8) {
            unsigned af[4][4];
#pragma unroll
            for (int i = 0; i < 4; i++) {
                int base = warp_m * 64 + i * 16;
                af[i][0] = f2tf32(Asb[(base + ar)     * AS_STRIDE + k8 + ac]);
                af[i][1] = f2tf32(Asb[(base + 8 + ar) * AS_STRIDE + k8 + ac]);
                af[i][2] = f2tf32(Asb[(base + ar)     * AS_STRIDE + k8 + 4 + ac]);
                af[i][3] = f2tf32(Asb[(base + 8 + ar) * AS_STRIDE + k8 + 4 + ac]);
            }
            unsigned bf[4][2];
#pragma unroll
            for (int j = 0; j < 4; j++) {
                int nbx = warp_n * 32 + j * 8 + ar;
                bf[j][0] = f2tf32(Bsb[(k8 + ac)     * BS_STRIDE + nbx]);
                bf[j][1] = f2tf32(Bsb[(k8 + 4 + ac) * BS_STRIDE + nbx]);
            }
#pragma unroll
            for (int i = 0; i < 4; i++)
#pragma unroll
                for (int j = 0; j < 4; j++) {
                    asm volatile(
                        "mma.sync.aligned.m16n8k8.row.col.f32.tf32.tf32.f32 "
                        "{%0,%1,%2,%3}, {%4,%5,%6,%7}, {%8,%9}, {%0,%1,%2,%3};"
                        : "+f"(c[i][j][0]), "+f"(c[i][j][1]),
                          "+f"(c[i][j][2]), "+f"(c[i][j][3])
                        : "r"(af[i][0]), "r"(af[i][1]),
                          "r"(af[i][2]), "r"(af[i][3]),
                          "r"(bf[j][0]), "r"(bf[j][1]));
                }
        }
        __syncthreads();
    }

#pragma unroll
    for (int j = 0; j < 4; j++) {
        int gn = n0 + warp_n * 32 + j * 8 + ac2;
#pragma unroll
        for (int i = 0; i < 4; i++) {
            int r0 = m0 + warp_m * 64 + i * 16 + ar;
            float2 v0 = make_float2(c[i][j][0], c[i][j][1]);
            float2 v1 = make_float2(c[i][j][2], c[i][j][3]);
            if (r0 < M)     *(float2*)(C + (size_t)r0 * LDAB + gn)       = v0;
            if (r0 + 8 < M) *(float2*)(C + (size_t)(r0 + 8) * LDAB + gn) = v1;
        }
    }
}

// ---------------------------------------------------------------- edge MLP
// warp handles 2 edges per iteration (grid-stride); consts hoisted.
__global__ void __launch_bounds__(256) edge_kernel(
    const int* __restrict__ ei, const float* __restrict__ AB,
    const float* __restrict__ bm1, const float* __restrict__ Wm2,
    const float* __restrict__ bm2, float* __restrict__ out,
    int E, int warpsTotal)
{
    int warpId = blockIdx.x * 8 + (threadIdx.x >> 5);
    int lane   = threadIdx.x & 31;
    int q0 = lane, q1 = lane + 32;

    const float4* bi = (const float4*)bm1;
    float4 cv0 = bi[q0], cv1 = bi[q1];
    const float4* w = (const float4*)Wm2;
    float4 w00 = w[q0 * 2], w01 = w[q0 * 2 + 1];
    float4 w10 = w[q1 * 2], w11 = w[q1 * 2 + 1];
    float bb0 = bm2[0], bb1 = bm2[1];

    for (int e = warpId * 2; e < E; e += warpsTotal * 2) {
        int e1 = e + 1;
        bool has2 = (e1 < E);
        int srcA = ei[e];
        int dstA = ei[E + e];
        int srcB = has2 ? ei[e1]     : srcA;
        int dstB = has2 ? ei[E + e1] : dstA;

        const float4* aA = (const float4*)(AB + (size_t)srcA * LDAB);
        const float4* bA = (const float4*)(AB + (size_t)dstA * LDAB + 256);
        const float4* aB = (const float4*)(AB + (size_t)srcB * LDAB);
        const float4* bB = (const float4*)(AB + (size_t)dstB * LDAB + 256);

        float4 aA0 = aA[q0], aA1 = aA[q1];
        float4 bA0 = bA[q0], bA1 = bA[q1];
        float4 aB0 = aB[q0], aB1 = aB[q1];
        float4 bB0 = bB[q0], bB1 = bB[q1];

        float accA0, accA1, accB0, accB1;
        {
            float h0 = fmaxf(aA0.x + bA0.x + cv0.x, 0.f);
            float h1 = fmaxf(aA0.y + bA0.y + cv0.y, 0.f);
            float h2 = fmaxf(aA0.z + bA0.z + cv0.z, 0.f);
            float h3 = fmaxf(aA0.w + bA0.w + cv0.w, 0.f);
            accA0 = h0 * w00.x;              accA1 = h0 * w00.y;
            accA0 = fmaf(h1, w00.z, accA0);  accA1 = fmaf(h1, w00.w, accA1);
            accA0 = fmaf(h2, w01.x, accA0);  accA1 = fmaf(h2, w01.y, accA1);
            accA0 = fmaf(h3, w01.z, accA0);  accA1 = fmaf(h3, w01.w, accA1);
            h0 = fmaxf(aA1.x + bA1.x + cv1.x, 0.f);
            h1 = fmaxf(aA1.y + bA1.y + cv1.y, 0.f);
            h2 = fmaxf(aA1.z + bA1.z + cv1.z, 0.f);
            h3 = fmaxf(aA1.w + bA1.w + cv1.w, 0.f);
            accA0 = fmaf(h0, w10.x, accA0);  accA1 = fmaf(h0, w10.y, accA1);
            accA0 = fmaf(h1, w10.z, accA0);  accA1 = fmaf(h1, w10.w, accA1);
            accA0 = fmaf(h2, w11.x, accA0);  accA1 = fmaf(h2, w11.y, accA1);
            accA0 = fmaf(h3, w11.z, accA0);  accA1 = fmaf(h3, w11.w, accA1);
        }
        {
            float h0 = fmaxf(aB0.x + bB0.x + cv0.x, 0.f);
            float h1 = fmaxf(aB0.y + bB0.y + cv0.y, 0.f);
            float h2 = fmaxf(aB0.z + bB0.z + cv0.z, 0.f);
            float h3 = fmaxf(aB0.w + bB0.w + cv0.w, 0.f);
            accB0 = h0 * w00.x;              accB1 = h0 * w00.y;
            accB0 = fmaf(h1, w00.z, accB0);  accB1 = fmaf(h1, w00.w, accB1);
            accB0 = fmaf(h2, w01.x, accB0);  accB1 = fmaf(h2, w01.y, accB1);
            accB0 = fmaf(h3, w01.z, accB0);  accB1 = fmaf(h3, w01.w, accB1);
            h0 = fmaxf(aB1.x + bB1.x + cv1.x, 0.f);
            h1 = fmaxf(aB1.y + bB1.y + cv1.y, 0.f);
            h2 = fmaxf(aB1.z + bB1.z + cv1.z, 0.f);
            h3 = fmaxf(aB1.w + bB1.w + cv1.w, 0.f);
            accB0 = fmaf(h0, w10.x, accB0);  accB1 = fmaf(h0, w10.y, accB1);
            accB0 = fmaf(h1, w10.z, accB0);  accB1 = fmaf(h1, w10.w, accB1);
            accB0 = fmaf(h2, w11.x, accB0);  accB1 = fmaf(h2, w11.y, accB1);
            accB0 = fmaf(h3, w11.z, accB0);  accB1 = fmaf(h3, w11.w, accB1);
        }
#pragma unroll
        for (int off = 16; off > 0; off >>= 1) {
            accA0 += __shfl_xor_sync(0xFFFFFFFFu, accA0, off);
            accA1 += __shfl_xor_sync(0xFFFFFFFFu, accA1, off);
            accB0 += __shfl_xor_sync(0xFFFFFFFFu, accB0, off);
            accB1 += __shfl_xor_sync(0xFFFFFFFFu, accB1, off);
        }
        if (lane == 0) {
            *(float2*)(out + (size_t)e * 2) = make_float2(accA0 + bb0, accA1 + bb1);
            if (has2)
                *(float2*)(out + (size_t)e1 * 2) = make_float2(accB0 + bb0, accB1 + bb1);
        }
    }
}

// ---------------------------------------------------------------- launch
extern "C" void kernel_launch(void* const* d_in, const int* in_sizes, int n_in,
                              void* d_out, int out_size)
{
    const float* x   = (const float*)d_in[0];
    const int*   ei  = (const int*)d_in[1];        // int32 [2, E]
    const float* W1l = (const float*)d_in[2];
    const float* b1l = (const float*)d_in[3];
    const float* W1r = (const float*)d_in[4];
    const float* W2l = (const float*)d_in[5];
    const float* b2l = (const float*)d_in[6];
    const float* W2r = (const float*)d_in[7];
    const float* Wm1 = (const float*)d_in[8];      // [512, 256]
    const float* bm1 = (const float*)d_in[9];
    const float* Wm2 = (const float*)d_in[10];     // [256, 2]
    const float* bm2 = (const float*)d_in[11];
    float*       out = (float*)d_out;

    int M = in_sizes[0] / D;       // 50000
    int E = in_sizes[1] / 2;       // 800000

    float *PQ, *rdeg, *h1, *h2, *AB;
    int *deg, *rowptr, *cursor, *elist;
    cudaGetSymbolAddress((void**)&PQ,     g_PQ);
    cudaGetSymbolAddress((void**)&rdeg,   g_rdeg);
    cudaGetSymbolAddress((void**)&h1,     g_h1);
    cudaGetSymbolAddress((void**)&h2,     g_h2);
    cudaGetSymbolAddress((void**)&AB,     g_AB);
    cudaGetSymbolAddress((void**)&deg,    g_deg);
    cudaGetSymbolAddress((void**)&rowptr, g_rowptr);
    cudaGetSymbolAddress((void**)&cursor, g_cursor);
    cudaGetSymbolAddress((void**)&elist,  g_elist);

    dim3 mgrid(LDAB / GBN, (M + GBM - 1) / GBM);   // (4, 391)
    int eb256 = (E + 255) / 256;
    int nblk  = (M + 7) / 8;

    // ---- CSR build (shared by both layers) ----
    zeroi_kernel<<<(M + 255) / 256, 256>>>(deg, M);
    hist_kernel<<<eb256, 256>>>(ei, deg, E);
    scan_kernel<<<1, 1024>>>(deg, rowptr, cursor, rdeg, M);
    fill_kernel<<<eb256, 256>>>(ei, cursor, elist, E);

    // ---- layer 1: PQ = x @ [W1l|W1r]; h1 = relu(agg(P) + Q + b1l) ----
    mma_gemm_kernel<<<mgrid, 256>>>(x, W1l, W1r, PQ, M);
    gatherf_kernel<<<nblk, 256>>>(rowptr, elist, rdeg, PQ, b1l, h1, M);

    // ---- layer 2 ----
    mma_gemm_kernel<<<mgrid, 256>>>(h1, W2l, W2r, PQ, M);
    gatherf_kernel<<<nblk, 256>>>(rowptr, elist, rdeg, PQ, b2l, h2, M);

    // ---- edge MLP node precompute: AB = h2 @ [Wm1_top | Wm1_bot] ----
    mma_gemm_kernel<<<mgrid, 256>>>(h2, Wm1, Wm1 + 256 * D, AB, M);

    // ---- per-edge ----
    int egrid = 6250;
    edge_kernel<<<egrid, 256>>>(ei, AB, bm1, Wm2, bm2, out, E, egrid * 8);
}

// round 15
// speedup vs baseline: 1.0661x; 1.0661x over previous
#include <cuda_runtime.h>
#include <cuda_bf16.h>

// ---------------------------------------------------------------------------
// EdgeClassifierGNN: 2x SAGEConv(mean) + edge MLP.
//   CSR built per call; aggregation = warp-per-node gather (no float atomics).
//   GEMMs: mma.sync m16n8k8 tf32, fp32 accumulate, cp.async double-buffered.
//   AB[:, :256]=h2@Wm1_top, AB[:,256:]=h2@Wm1_bot in one merged GEMM.
//   out[e] = relu(AB[src,:256]+AB[dst,256:]+bm1) @ Wm2 + bm2
// NOTE: gathered operands (x, h1, msg) stay in dense 256-wide 51MB buffers so
// the gather hot-set fits L2; the R12 PQ-based variant spilled L2 and lost.
// ---------------------------------------------------------------------------

#define MAXN 50000
#define MAXE 800000
#define D 256
#define LDAB 512

__device__ __align__(16) float g_msg [(size_t)MAXN * D];
__device__ __align__(16) float g_rdeg[MAXN];
__device__ __align__(16) float g_h1  [(size_t)MAXN * D];
__device__ __align__(16) float g_h2  [(size_t)MAXN * D];
__device__ __align__(16) float g_AB  [(size_t)MAXN * LDAB];
__device__ int g_deg   [MAXN];
__device__ int g_rowptr[MAXN + 1];
__device__ int g_cursor[MAXN];
__device__ int g_elist [MAXE];

// ---------------------------------------------------------------- zero int
__global__ void zeroi_kernel(int* __restrict__ p, int n) {
    int i = blockIdx.x * blockDim.x + threadIdx.x;
    if (i < n) p[i] = 0;
}

// ---------------------------------------------------------------- histogram
__global__ void hist_kernel(const int* __restrict__ ei, int* __restrict__ deg,
                            int E)
{
    int e = blockIdx.x * blockDim.x + threadIdx.x;
    if (e < E) atomicAdd(deg + ei[E + e], 1);
}

// ---------------------------------------------------------------- scan
__global__ void scan_kernel(const int* __restrict__ deg,
                            int* __restrict__ rowptr, int* __restrict__ cursor,
                            float* __restrict__ rdeg, int n)
{
    __shared__ int sdata[1024];
    __shared__ int carry_s;
    if (threadIdx.x == 0) carry_s = 0;
    __syncthreads();

    for (int base = 0; base < n; base += 1024) {
        int i = base + threadIdx.x;
        int v = (i < n) ? deg[i] : 0;
        sdata[threadIdx.x] = v;
        __syncthreads();
#pragma unroll
        for (int off = 1; off < 1024; off <<= 1) {
            int t = (threadIdx.x >= off) ? sdata[threadIdx.x - off] : 0;
            __syncthreads();
            sdata[threadIdx.x] += t;
            __syncthreads();
        }
        int incl = sdata[threadIdx.x] + carry_s;
        if (i < n) {
            rowptr[i + 1] = incl;
            cursor[i]     = incl - v;
            rdeg[i]       = 1.0f / fmaxf((float)v, 1.0f);
        }
        __syncthreads();
        if (threadIdx.x == 1023) carry_s = incl;
        __syncthreads();
    }
    if (threadIdx.x == 0) rowptr[0] = 0;
}

// ---------------------------------------------------------------- fill
__global__ void fill_kernel(const int* __restrict__ ei, int* __restrict__ cursor,
                            int* __restrict__ elist, int E)
{
    int e = blockIdx.x * blockDim.x + threadIdx.x;
    if (e >= E) return;
    int p = atomicAdd(cursor + ei[E + e], 1);
    elist[p] = ei[e];              // store src
}

// ---------------------------------------------------------------- gather agg
// warp per node: out[node] = rdeg[node] * sum_{s in row} X[s]   (unroll 4)
__global__ void __launch_bounds__(256) gather_kernel(
    const int* __restrict__ rowptr, const int* __restrict__ elist,
    const float* __restrict__ rdeg, const float* __restrict__ X,
    float* __restrict__ out, int M)
{
    int node = blockIdx.x * 8 + (threadIdx.x >> 5);
    if (node >= M) return;
    int lane = threadIdx.x & 31;
    int q0 = lane, q1 = lane + 32;
    int beg = rowptr[node], end = rowptr[node + 1];

    float4 a0 = make_float4(0.f, 0.f, 0.f, 0.f);
    float4 a1 = make_float4(0.f, 0.f, 0.f, 0.f);

    int i = beg;
    for (; i + 3 < end; i += 4) {
        int s0 = elist[i],     s1 = elist[i + 1];
        int s2 = elist[i + 2], s3 = elist[i + 3];
        const float4* x0 = (const float4*)(X + (size_t)s0 * D);
        const float4* x1 = (const float4*)(X + (size_t)s1 * D);
        const float4* x2 = (const float4*)(X + (size_t)s2 * D);
        const float4* x3 = (const float4*)(X + (size_t)s3 * D);
        float4 u0 = x0[q0], v0 = x1[q0], w0 = x2[q0], z0 = x3[q0];
        float4 u1 = x0[q1], v1 = x1[q1], w1 = x2[q1], z1 = x3[q1];
        a0.x += (u0.x + v0.x) + (w0.x + z0.x);
        a0.y += (u0.y + v0.y) + (w0.y + z0.y);
        a0.z += (u0.z + v0.z) + (w0.z + z0.z);
        a0.w += (u0.w + v0.w) + (w0.w + z0.w);
        a1.x += (u1.x + v1.x) + (w1.x + z1.x);
        a1.y += (u1.y + v1.y) + (w1.y + z1.y);
        a1.z += (u1.z + v1.z) + (w1.z + z1.z);
        a1.w += (u1.w + v1.w) + (w1.w + z1.w);
    }
    for (; i < end; i++) {
        int s0 = elist[i];
        const float4* x0 = (const float4*)(X + (size_t)s0 * D);
        float4 u0 = x0[q0], u1 = x0[q1];
        a0.x += u0.x; a0.y += u0.y; a0.z += u0.z; a0.w += u0.w;
        a1.x += u1.x; a1.y += u1.y; a1.z += u1.z; a1.w += u1.w;
    }

    float r = rdeg[node];
    a0.x *= r; a0.y *= r; a0.z *= r; a0.w *= r;
    a1.x *= r; a1.y *= r; a1.z *= r; a1.w *= r;
    float4* o = (float4*)(out + (size_t)node * D);
    o[q0] = a0;
    o[q1] = a1;
}

// ---------------------------------------------------------------- tf32 GEMM
// C[M, ncols] = act( A1@B1 + A2@B2 + bias ), K = 256 per source phase.
// When B1hi != nullptr (single-phase only): blocks with n0 >= 256 use B1hi
// with column offset n0-256 (merged [Wm1_top | Wm1_bot] output).
#define GBM 128
#define GBN 128
#define GBK 16
#define AS_STRIDE 20
#define BS_STRIDE 136
#define KSTEPS (D / GBK)   // 16

__device__ __forceinline__ unsigned f2tf32(float f) {
    unsigned u;
    asm("cvt.rna.tf32.f32 %0, %1;" : "=r"(u) : "f"(f));
    return u;
}

__device__ __forceinline__ void cpa16(unsigned dst, const void* src, int nbytes) {
    asm volatile("cp.async.cg.shared.global [%0], [%1], 16, %2;\n"
                 :: "r"(dst), "l"(src), "r"(nbytes));
}

__global__ void __launch_bounds__(256) mma_gemm_kernel(
    const float* __restrict__ A1, const float* __restrict__ B1,
    const float* __restrict__ A2, const float* __restrict__ B2,
    const float* __restrict__ B1hi, const float* __restrict__ bias,
    float* __restrict__ C, int M, int ldc, int relu)
{
    __shared__ float As[2][GBM * AS_STRIDE];
    __shared__ float Bs[2][GBK * BS_STRIDE];

    int tid    = threadIdx.x;
    int warp   = tid >> 5;
    int lane   = tid & 31;
    int warp_m = warp >> 2;
    int warp_n = warp & 3;
    int m0 = blockIdx.y * GBM;
    int n0 = blockIdx.x * GBN;

    const float* Bg0 = B1;
    int nb0 = n0;
    if (B1hi != nullptr && n0 >= 256) { Bg0 = B1hi; nb0 = n0 - 256; }

    int ar  = lane >> 2;
    int ac  = lane & 3;
    int ac2 = ac * 2;

    float c[4][4][4];
#pragma unroll
    for (int i = 0; i < 4; i++)
#pragma unroll
        for (int j = 0; j < 4; j++)
#pragma unroll
            for (int r = 0; r < 4; r++) c[i][j][r] = 0.f;

    int nphase = (A2 != nullptr) ? 2 : 1;
    int niter  = nphase * KSTEPS;

    unsigned asb[2], bsb[2];
    asb[0] = (unsigned)__cvta_generic_to_shared(&As[0][0]);
    asb[1] = (unsigned)__cvta_generic_to_shared(&As[1][0]);
    bsb[0] = (unsigned)__cvta_generic_to_shared(&Bs[0][0]);
    bsb[1] = (unsigned)__cvta_generic_to_shared(&Bs[1][0]);

    auto issue = [&](int t, int buf) {
        int ph = t >> 4;                       // KSTEPS == 16
        int k0 = (t & (KSTEPS - 1)) * GBK;
        const float* Ag = ph ? A2 : A1;
        const float* Bg = ph ? B2 : Bg0;
        int nb = ph ? n0 : nb0;
#pragma unroll
        for (int u = 0; u < 2; u++) {
            int idx = u * 256 + tid;
            int row = idx >> 2;
            int kq  = (idx & 3) * 4;
            int gm  = m0 + row;
            bool ok = (gm < M);
            const float* src = Ag + (size_t)(ok ? gm : 0) * D + k0 + kq;
            cpa16(asb[buf] + (unsigned)(row * AS_STRIDE + kq) * 4, src, ok ? 16 : 0);
        }
#pragma unroll
        for (int u = 0; u < 2; u++) {
            int idx = u * 256 + tid;
            int row = idx >> 5;
            int nq  = (idx & 31) * 4;
            cpa16(bsb[buf] + (unsigned)(row * BS_STRIDE + nq) * 4,
                  Bg + (size_t)(k0 + row) * D + nb + nq, 16);
        }
        asm volatile("cp.async.commit_group;\n" ::: "memory");
    };

    issue(0, 0);

    for (int t = 0; t < niter; t++) {
        int buf = t & 1;
        if (t + 1 < niter) {
            issue(t + 1, buf ^ 1);
            asm volatile("cp.async.wait_group 1;\n" ::: "memory");
        } else {
            asm volatile("cp.async.wait_group 0;\n" ::: "memory");
        }
        __syncthreads();

        const float* Asb = As[buf];
        const float* Bsb = Bs[buf];
#pragma unroll
        for (int k8 = 0; k8 < GBK; k8 += 8) {
            unsigned af[4][4];
#pragma unroll
            for (int i = 0; i < 4; i++) {
                int base = warp_m * 64 + i * 16;
                af[i][0] = f2tf32(Asb[(base + ar)     * AS_STRIDE + k8 + ac]);
                af[i][1] = f2tf32(Asb[(base + 8 + ar) * AS_STRIDE + k8 + ac]);
                af[i][2] = f2tf32(Asb[(base + ar)     * AS_STRIDE + k8 + 4 + ac]);
                af[i][3] = f2tf32(Asb[(base + 8 + ar) * AS_STRIDE + k8 + 4 + ac]);
            }
            unsigned bf[4][2];
#pragma unroll
            for (int j = 0; j < 4; j++) {
                int nbx = warp_n * 32 + j * 8 + ar;
                bf[j][0] = f2tf32(Bsb[(k8 + ac)     * BS_STRIDE + nbx]);
                bf[j][1] = f2tf32(Bsb[(k8 + 4 + ac) * BS_STRIDE + nbx]);
            }
#pragma unroll
            for (int i = 0; i < 4; i++)
#pragma unroll
                for (int j = 0; j < 4; j++) {
                    asm volatile(
                        "mma.sync.aligned.m16n8k8.row.col.f32.tf32.tf32.f32 "
                        "{%0,%1,%2,%3}, {%4,%5,%6,%7}, {%8,%9}, {%0,%1,%2,%3};"
                        : "+f"(c[i][j][0]), "+f"(c[i][j][1]),
                          "+f"(c[i][j][2]), "+f"(c[i][j][3])
                        : "r"(af[i][0]), "r"(af[i][1]),
                          "r"(af[i][2]), "r"(af[i][3]),
                          "r"(bf[j][0]), "r"(bf[j][1]));
                }
        }
        __syncthreads();
    }

#pragma unroll
    for (int j = 0; j < 4; j++) {
        int gn = n0 + warp_n * 32 + j * 8 + ac2;
        float2 bv = make_float2(0.f, 0.f);
        if (bias != nullptr) bv = *(const float2*)(bias + gn);
#pragma unroll
        for (int i = 0; i < 4; i++) {
            int r0 = m0 + warp_m * 64 + i * 16 + ar;
            float2 v0 = make_float2(c[i][j][0] + bv.x, c[i][j][1] + bv.y);
            float2 v1 = make_float2(c[i][j][2] + bv.x, c[i][j][3] + bv.y);
            if (relu) {
                v0.x = fmaxf(v0.x, 0.f); v0.y = fmaxf(v0.y, 0.f);
                v1.x = fmaxf(v1.x, 0.f); v1.y = fmaxf(v1.y, 0.f);
            }
            if (r0 < M)     *(float2*)(C + (size_t)r0 * ldc + gn)       = v0;
            if (r0 + 8 < M) *(float2*)(C + (size_t)(r0 + 8) * ldc + gn) = v1;
        }
    }
}

// ---------------------------------------------------------------- edge MLP
// warp handles 2 edges per iteration (grid-stride); consts hoisted.
__global__ void __launch_bounds__(256) edge_kernel(
    const int* __restrict__ ei, const float* __restrict__ AB,
    const float* __restrict__ bm1, const float* __restrict__ Wm2,
    const float* __restrict__ bm2, float* __restrict__ out,
    int E, int warpsTotal)
{
    int warpId = blockIdx.x * 8 + (threadIdx.x >> 5);
    int lane   = threadIdx.x & 31;
    int q0 = lane, q1 = lane + 32;

    const float4* bi = (const float4*)bm1;
    float4 cv0 = bi[q0], cv1 = bi[q1];
    const float4* w = (const float4*)Wm2;
    float4 w00 = w[q0 * 2], w01 = w[q0 * 2 + 1];
    float4 w10 = w[q1 * 2], w11 = w[q1 * 2 + 1];
    float bb0 = bm2[0], bb1 = bm2[1];

    for (int e = warpId * 2; e < E; e += warpsTotal * 2) {
        int e1 = e + 1;
        bool has2 = (e1 < E);
        int srcA = ei[e];
        int dstA = ei[E + e];
        int srcB = has2 ? ei[e1]     : srcA;
        int dstB = has2 ? ei[E + e1] : dstA;

        const float4* aA = (const float4*)(AB + (size_t)srcA * LDAB);
        const float4* bA = (const float4*)(AB + (size_t)dstA * LDAB + 256);
        const float4* aB = (const float4*)(AB + (size_t)srcB * LDAB);
        const float4* bB = (const float4*)(AB + (size_t)dstB * LDAB + 256);

        float4 aA0 = aA[q0], aA1 = aA[q1];
        float4 bA0 = bA[q0], bA1 = bA[q1];
        float4 aB0 = aB[q0], aB1 = aB[q1];
        float4 bB0 = bB[q0], bB1 = bB[q1];

        float accA0, accA1, accB0, accB1;
        {
            float h0 = fmaxf(aA0.x + bA0.x + cv0.x, 0.f);
            float h1 = fmaxf(aA0.y + bA0.y + cv0.y, 0.f);
            float h2 = fmaxf(aA0.z + bA0.z + cv0.z, 0.f);
            float h3 = fmaxf(aA0.w + bA0.w + cv0.w, 0.f);
            accA0 = h0 * w00.x;              accA1 = h0 * w00.y;
            accA0 = fmaf(h1, w00.z, accA0);  accA1 = fmaf(h1, w00.w, accA1);
            accA0 = fmaf(h2, w01.x, accA0);  accA1 = fmaf(h2, w01.y, accA1);
            accA0 = fmaf(h3, w01.z, accA0);  accA1 = fmaf(h3, w01.w, accA1);
            h0 = fmaxf(aA1.x + bA1.x + cv1.x, 0.f);
            h1 = fmaxf(aA1.y + bA1.y + cv1.y, 0.f);
            h2 = fmaxf(aA1.z + bA1.z + cv1.z, 0.f);
            h3 = fmaxf(aA1.w + bA1.w + cv1.w, 0.f);
            accA0 = fmaf(h0, w10.x, accA0);  accA1 = fmaf(h0, w10.y, accA1);
            accA0 = fmaf(h1, w10.z, accA0);  accA1 = fmaf(h1, w10.w, accA1);
            accA0 = fmaf(h2, w11.x, accA0);  accA1 = fmaf(h2, w11.y, accA1);
            accA0 = fmaf(h3, w11.z, accA0);  accA1 = fmaf(h3, w11.w, accA1);
        }
        {
            float h0 = fmaxf(aB0.x + bB0.x + cv0.x, 0.f);
            float h1 = fmaxf(aB0.y + bB0.y + cv0.y, 0.f);
            float h2 = fmaxf(aB0.z + bB0.z + cv0.z, 0.f);
            float h3 = fmaxf(aB0.w + bB0.w + cv0.w, 0.f);
            accB0 = h0 * w00.x;              accB1 = h0 * w00.y;
            accB0 = fmaf(h1, w00.z, accB0);  accB1 = fmaf(h1, w00.w, accB1);
            accB0 = fmaf(h2, w01.x, accB0);  accB1 = fmaf(h2, w01.y, accB1);
            accB0 = fmaf(h3, w01.z, accB0);  accB1 = fmaf(h3, w01.w, accB1);
            h0 = fmaxf(aB1.x + bB1.x + cv1.x, 0.f);
            h1 = fmaxf(aB1.y + bB1.y + cv1.y, 0.f);
            h2 = fmaxf(aB1.z + bB1.z + cv1.z, 0.f);
            h3 = fmaxf(aB1.w + bB1.w + cv1.w, 0.f);
            accB0 = fmaf(h0, w10.x, accB0);  accB1 = fmaf(h0, w10.y, accB1);
            accB0 = fmaf(h1, w10.z, accB0);  accB1 = fmaf(h1, w10.w, accB1);
            accB0 = fmaf(h2, w11.x, accB0);  accB1 = fmaf(h2, w11.y, accB1);
            accB0 = fmaf(h3, w11.z, accB0);  accB1 = fmaf(h3, w11.w, accB1);
        }
#pragma unroll
        for (int off = 16; off > 0; off >>= 1) {
            accA0 += __shfl_xor_sync(0xFFFFFFFFu, accA0, off);
            accA1 += __shfl_xor_sync(0xFFFFFFFFu, accA1, off);
            accB0 += __shfl_xor_sync(0xFFFFFFFFu, accB0, off);
            accB1 += __shfl_xor_sync(0xFFFFFFFFu, accB1, off);
        }
        if (lane == 0) {
            *(float2*)(out + (size_t)e * 2) = make_float2(accA0 + bb0, accA1 + bb1);
            if (has2)
                *(float2*)(out + (size_t)e1 * 2) = make_float2(accB0 + bb0, accB1 + bb1);
        }
    }
}

// ---------------------------------------------------------------- launch
extern "C" void kernel_launch(void* const* d_in, const int* in_sizes, int n_in,
                              void* d_out, int out_size)
{
    const float* x   = (const float*)d_in[0];
    const int*   ei  = (const int*)d_in[1];        // int32 [2, E]
    const float* W1l = (const float*)d_in[2];
    const float* b1l = (const float*)d_in[3];
    const float* W1r = (const float*)d_in[4];
    const float* W2l = (const float*)d_in[5];
    const float* b2l = (const float*)d_in[6];
    const float* W2r = (const float*)d_in[7];
    const float* Wm1 = (const float*)d_in[8];      // [512, 256]
    const float* bm1 = (const float*)d_in[9];
    const float* Wm2 = (const float*)d_in[10];     // [256, 2]
    const float* bm2 = (const float*)d_in[11];
    float*       out = (float*)d_out;

    int M = in_sizes[0] / D;       // 50000
    int E = in_sizes[1] / 2;       // 800000

    float *msg, *rdeg, *h1, *h2, *AB;
    int *deg, *rowptr, *cursor, *elist;
    cudaGetSymbolAddress((void**)&msg,    g_msg);
    cudaGetSymbolAddress((void**)&rdeg,   g_rdeg);
    cudaGetSymbolAddress((void**)&h1,     g_h1);
    cudaGetSymbolAddress((void**)&h2,     g_h2);
    cudaGetSymbolAddress((void**)&AB,     g_AB);
    cudaGetSymbolAddress((void**)&deg,    g_deg);
    cudaGetSymbolAddress((void**)&rowptr, g_rowptr);
    cudaGetSymbolAddress((void**)&cursor, g_cursor);
    cudaGetSymbolAddress((void**)&elist,  g_elist);

    dim3 ggrid(D / GBN, (M + GBM - 1) / GBM);      // (2, 391)
    dim3 mgrid(LDAB / GBN, (M + GBM - 1) / GBM);   // (4, 391)
    int eb256 = (E + 255) / 256;
    int nblk  = (M + 7) / 8;

    // ---- CSR build (shared by both layers) ----
    zeroi_kernel<<<(M + 255) / 256, 256>>>(deg, M);
    hist_kernel<<<eb256, 256>>>(ei, deg, E);
    scan_kernel<<<1, 1024>>>(deg, rowptr, cursor, rdeg, M);
    fill_kernel<<<eb256, 256>>>(ei, cursor, elist, E);

    // ---- layer 1 ----
    gather_kernel<<<nblk, 256>>>(rowptr, elist, rdeg, x, msg, M);
    mma_gemm_kernel<<<ggrid, 256>>>(msg, W1l, x, W1r, nullptr, b1l,
                                    h1, M, D, 1);

    // ---- layer 2 ----
    gather_kernel<<<nblk, 256>>>(rowptr, elist, rdeg, h1, msg, M);
    mma_gemm_kernel<<<ggrid, 256>>>(msg, W2l, h1, W2r, nullptr, b2l,
                                    h2, M, D, 1);

    // ---- edge MLP node precompute (merged A|B, one GEMM) ----
    mma_gemm_kernel<<<mgrid, 256>>>(h2, Wm1, nullptr, nullptr,
                                    Wm1 + 256 * D, nullptr, AB, M, LDAB, 0);

    // ---- per-edge ----
    int egrid = 6250;
    edge_kernel<<<egrid, 256>>>(ei, AB, bm1, Wm2, bm2, out, E, egrid * 8);
}